// round 2
// baseline (speedup 1.0000x reference)
#include <cuda_runtime.h>
#include <cstdint>

#define B_ 8
#define T_ 1024
#define D_ 768
#define H_ 12
#define HD_ 64
#define BT_ (B_*T_)          // 8192
#define BH_ (B_*H_)          // 96

// ---------------- scratch (static device globals; no allocation) --------------
__device__ float g_q[BT_*D_];
__device__ float g_k[BT_*D_];
__device__ float g_v[BT_*D_];
__device__ float g_o[BT_*D_];
__device__ float g_g1[BH_*T_];

// ---------------- gate kernel -------------------------------------------------
// g1[b,h,t] = a*(b*grep[h]-1)+2,  a=sig(x_h·wA+bA), b=sig(x_h·wB+bB)
__global__ void gate_kernel(const float* __restrict__ x,
                            const float* __restrict__ Wg,
                            const float* __restrict__ bg,
                            const float* __restrict__ grep,
                            float* __restrict__ g1)
{
    __shared__ float wA[HD_], wB[HD_], bsum[2];
    int tid = threadIdx.x;
    if (tid < HD_) {
        float sa = 0.f, sb = 0.f;
        #pragma unroll
        for (int j = 0; j < 4; j++) sa += Wg[tid*8 + j];
        #pragma unroll
        for (int j = 4; j < 8; j++) sb += Wg[tid*8 + j];
        wA[tid] = sa; wB[tid] = sb;
    }
    if (tid == 0) {
        bsum[0] = bg[0]+bg[1]+bg[2]+bg[3];
        bsum[1] = bg[4]+bg[5]+bg[6]+bg[7];
    }
    __syncthreads();

    int idx = blockIdx.x * blockDim.x + tid;    // idx = (b*T + t)*H + h
    if (idx >= BT_*H_) return;
    const float* xp = x + (size_t)idx * HD_;
    float sa = bsum[0], sb = bsum[1];
    #pragma unroll 8
    for (int d = 0; d < HD_; d++) {
        float xv = xp[d];
        sa += xv * wA[d];
        sb += xv * wB[d];
    }
    float a  = 1.f / (1.f + __expf(-sa));
    float bb = 1.f / (1.f + __expf(-sb));
    int h = idx % H_;
    int t = (idx / H_) % T_;
    int b = idx / (H_ * T_);
    float g = a * (bb * grep[h] - 1.0f) + 2.0f;
    g1[(b*H_ + h)*T_ + t] = g;
}

// ---------------- SGEMM: C = A(MxK) @ W(KxN) + bias ---------------------------
// K = N = 768. remap=1: store into (B,H,T,HD) head-split layout.
__global__ __launch_bounds__(256, 2)
void sgemm_kernel(const float* __restrict__ A,
                  const float* __restrict__ W,
                  const float* __restrict__ bias,
                  float* __restrict__ C,
                  int remap)
{
    const int K = D_, N = D_;
    __shared__ float As[8][128];
    __shared__ float Bs[8][128];

    int tid  = threadIdx.x;
    int row0 = blockIdx.y * 128;
    int col0 = blockIdx.x * 128;
    int tm = (tid / 16) * 8;
    int tn = (tid % 16) * 8;

    float acc[8][8];
    #pragma unroll
    for (int i = 0; i < 8; i++)
        #pragma unroll
        for (int j = 0; j < 8; j++) acc[i][j] = 0.f;

    int arow = tid >> 1;             // 0..127
    int acol = (tid & 1) * 4;        // 0 or 4
    int brow = tid >> 5;             // 0..7
    int bcol = (tid & 31) * 4;       // 0..124

    const float* Ap = A + (size_t)(row0 + arow) * K + acol;
    const float* Wp = W + (size_t)brow * N + col0 + bcol;

    for (int kt = 0; kt < K; kt += 8) {
        float4 av = *(const float4*)(Ap + kt);
        float4 bv = *(const float4*)(Wp + (size_t)kt * N);
        __syncthreads();
        As[acol+0][arow] = av.x;
        As[acol+1][arow] = av.y;
        As[acol+2][arow] = av.z;
        As[acol+3][arow] = av.w;
        *(float4*)&Bs[brow][bcol] = bv;
        __syncthreads();
        #pragma unroll
        for (int kk = 0; kk < 8; kk++) {
            float ra[8], rb[8];
            #pragma unroll
            for (int i = 0; i < 8; i++) ra[i] = As[kk][tm + i];
            #pragma unroll
            for (int j = 0; j < 8; j++) rb[j] = Bs[kk][tn + j];
            #pragma unroll
            for (int i = 0; i < 8; i++)
                #pragma unroll
                for (int j = 0; j < 8; j++)
                    acc[i][j] += ra[i] * rb[j];
        }
    }

    // store with bias (+ optional head-split remap)
    #pragma unroll
    for (int i = 0; i < 8; i++) {
        int m = row0 + tm + i;
        int b = m >> 10;            // /T_
        int t = m & (T_ - 1);
        #pragma unroll
        for (int j4 = 0; j4 < 8; j4 += 4) {
            int n = col0 + tn + j4;
            float4 val;
            val.x = acc[i][j4+0] + bias[n+0];
            val.y = acc[i][j4+1] + bias[n+1];
            val.z = acc[i][j4+2] + bias[n+2];
            val.w = acc[i][j4+3] + bias[n+3];
            if (remap) {
                int h = n >> 6;
                int d = n & 63;
                *(float4*)&C[(((size_t)b*H_ + h)*T_ + t)*HD_ + d] = val;
            } else {
                *(float4*)&C[(size_t)m * N + n] = val;
            }
        }
    }
}

// ---------------- flash attention kernel --------------------------------------
// grid: (T/64, B*H), block 256 (8 warps, 8 q-rows each, 2 k-cols per lane)
__global__ __launch_bounds__(256, 2)
void flash_kernel(const float* __restrict__ q,
                  const float* __restrict__ k,
                  const float* __restrict__ v,
                  const float* __restrict__ rel,
                  const float* __restrict__ mask,
                  const float* __restrict__ g1,
                  float* __restrict__ o)
{
    extern __shared__ float sm[];
    float* Qs = sm;                      // [64][64]
    float* Ks = Qs + 64*64;              // [64][65] transposed: Ks[d][k]
    float* Vs = Ks + 64*65;              // [64][64] natural: Vs[k][d]
    float* Rs = Vs + 64*64;              // [64][65] transposed: Rs[q][k]
    float* Ps = Rs + 64*65;              // [64][64] probs
    float* Ms = Ps + 64*64;              // [64] mask
    float* Gs = Ms + 64;                 // [64] gate

    int bh = blockIdx.y;
    int b  = bh / H_;
    int h  = bh % H_;
    int q0 = blockIdx.x * 64;
    int tid  = threadIdx.x;
    int warp = tid >> 5;
    int lane = tid & 31;
    int r0 = warp * 8;

    const float* qptr = q + ((size_t)bh * T_ + q0) * HD_;
    // load Q tile + gate row values
    for (int i = tid; i < 64*16; i += 256) {    // 1024 float4s
        int r  = i >> 4;
        int c4 = (i & 15) * 4;
        *(float4*)&Qs[r*64 + c4] = *(const float4*)&qptr[(size_t)r*HD_ + c4];
    }
    if (tid < 64) Gs[tid] = g1[(size_t)bh * T_ + q0 + tid];

    float m_i[8], l_i[8];
    float2 o_i[8];
    #pragma unroll
    for (int r = 0; r < 8; r++) {
        m_i[r] = -1e30f; l_i[r] = 0.f;
        o_i[r] = make_float2(0.f, 0.f);
    }

    const float* kbase = k + (size_t)bh * T_ * HD_;
    const float* vbase = v + (size_t)bh * T_ * HD_;
    const float* rbase = rel + (size_t)bh * T_ * T_;

    for (int kt = 0; kt < T_; kt += 64) {
        __syncthreads();
        // K tile transposed into Ks[d][k] (stride 65 -> conflict-free stores)
        for (int i = tid; i < 4096; i += 256) {
            int kk = i >> 6, d = i & 63;
            Ks[d*65 + kk] = kbase[(size_t)(kt + kk)*HD_ + d];
        }
        // V tile natural
        for (int i = tid; i < 1024; i += 256) {
            int kk = i >> 4;
            int d4 = (i & 15) * 4;
            *(float4*)&Vs[kk*64 + d4] = *(const float4*)&vbase[(size_t)(kt + kk)*HD_ + d4];
        }
        // rel_bias tile: global rows are k-major contiguous in q -> transpose into Rs[q][k]
        for (int i = tid; i < 4096; i += 256) {
            int kk = i >> 6, qq = i & 63;
            Rs[qq*65 + kk] = rbase[(size_t)(kt + kk)*T_ + q0 + qq];
        }
        if (tid < 64) Ms[tid] = mask[(size_t)b*T_ + kt + tid];
        __syncthreads();

        // ---- S = Q @ K^T ----
        float a0[8], a1[8];
        #pragma unroll
        for (int r = 0; r < 8; r++) { a0[r] = 0.f; a1[r] = 0.f; }
        #pragma unroll 4
        for (int d = 0; d < 64; d++) {
            float kv0 = Ks[d*65 + 2*lane];
            float kv1 = Ks[d*65 + 2*lane + 1];
            #pragma unroll
            for (int r = 0; r < 8; r++) {
                float qv = Qs[(r0 + r)*64 + d];
                a0[r] += qv * kv0;
                a1[r] += qv * kv1;
            }
        }

        float mk0 = Ms[2*lane], mk1 = Ms[2*lane + 1];
        // ---- bias + online softmax (per-warp rows) ----
        #pragma unroll
        for (int r = 0; r < 8; r++) {
            float g = Gs[r0 + r];
            float s0 = a0[r]*0.125f + g*Rs[(r0+r)*65 + 2*lane]     + mk0;
            float s1 = a1[r]*0.125f + g*Rs[(r0+r)*65 + 2*lane + 1] + mk1;
            float mt = fmaxf(s0, s1);
            #pragma unroll
            for (int off = 16; off > 0; off >>= 1)
                mt = fmaxf(mt, __shfl_xor_sync(0xffffffffu, mt, off));
            float mnew = fmaxf(m_i[r], mt);
            float p0 = __expf(s0 - mnew);
            float p1 = __expf(s1 - mnew);
            float alpha = __expf(m_i[r] - mnew);
            m_i[r] = mnew;
            float ps = p0 + p1;
            #pragma unroll
            for (int off = 16; off > 0; off >>= 1)
                ps += __shfl_xor_sync(0xffffffffu, ps, off);
            l_i[r] = l_i[r] * alpha + ps;
            o_i[r].x *= alpha;
            o_i[r].y *= alpha;
            *(float2*)&Ps[(r0+r)*64 + 2*lane] = make_float2(p0, p1);
        }
        __syncwarp();

        // ---- O += P @ V ----
        #pragma unroll 4
        for (int kk = 0; kk < 64; kk++) {
            float2 vv = *(float2*)&Vs[kk*64 + 2*lane];
            #pragma unroll
            for (int r = 0; r < 8; r++) {
                float p = Ps[(r0+r)*64 + kk];
                o_i[r].x += p * vv.x;
                o_i[r].y += p * vv.y;
            }
        }
    }

    // epilogue: normalize, merge heads into (B,T,D)
    #pragma unroll
    for (int r = 0; r < 8; r++) {
        float inv = 1.f / l_i[r];
        int qrow = q0 + r0 + r;
        float2 ov = make_float2(o_i[r].x * inv, o_i[r].y * inv);
        *(float2*)&o[((size_t)b*T_ + qrow)*D_ + h*HD_ + 2*lane] = ov;
    }
}

// ---------------- launch ------------------------------------------------------
extern "C" void kernel_launch(void* const* d_in, const int* in_sizes, int n_in,
                              void* d_out, int out_size)
{
    const float* x    = (const float*)d_in[0];
    const float* mask = (const float*)d_in[1];
    const float* rel  = (const float*)d_in[2];
    const float* Wq   = (const float*)d_in[3];
    const float* bq   = (const float*)d_in[4];
    const float* Wk   = (const float*)d_in[5];
    const float* bk   = (const float*)d_in[6];
    const float* Wv   = (const float*)d_in[7];
    const float* bv   = (const float*)d_in[8];
    const float* Wo   = (const float*)d_in[9];
    const float* bo   = (const float*)d_in[10];
    const float* Wg   = (const float*)d_in[11];
    const float* bg   = (const float*)d_in[12];
    const float* grep = (const float*)d_in[13];
    float* out = (float*)d_out;

    float *qb, *kb, *vb, *ob, *g1b;
    cudaGetSymbolAddress((void**)&qb,  g_q);
    cudaGetSymbolAddress((void**)&kb,  g_k);
    cudaGetSymbolAddress((void**)&vb,  g_v);
    cudaGetSymbolAddress((void**)&ob,  g_o);
    cudaGetSymbolAddress((void**)&g1b, g_g1);

    gate_kernel<<<(BT_*H_)/256, 256>>>(x, Wg, bg, grep, g1b);

    dim3 gg(D_/128, BT_/128);   // (6, 64)
    sgemm_kernel<<<gg, 256>>>(x, Wq, bq, qb, 1);
    sgemm_kernel<<<gg, 256>>>(x, Wk, bk, kb, 1);
    sgemm_kernel<<<gg, 256>>>(x, Wv, bv, vb, 1);

    const int SMEM = (64*64 + 64*65 + 64*64 + 64*65 + 64*64 + 64 + 64) * 4; // 82944 B
    cudaFuncSetAttribute(flash_kernel, cudaFuncAttributeMaxDynamicSharedMemorySize, SMEM);
    flash_kernel<<<dim3(T_/64, BH_), 256, SMEM>>>(qb, kb, vb, rel, mask, g1b, ob);

    sgemm_kernel<<<gg, 256>>>(ob, Wo, bo, out, 0);
}

// round 4
// speedup vs baseline: 2.0889x; 2.0889x over previous
#include <cuda_runtime.h>
#include <cstdint>

#define B_ 8
#define T_ 1024
#define D_ 768
#define H_ 12
#define HD_ 64
#define BT_ (B_*T_)          // 8192
#define BH_ (B_*H_)          // 96

// ---------------- scratch (static device globals; no allocation) --------------
__device__ float g_q[BT_*D_];
__device__ float g_k[BT_*D_];
__device__ float g_v[BT_*D_];
__device__ float g_o[BT_*D_];
__device__ float g_g1[BH_*T_];

// ---------------- helpers -----------------------------------------------------
__device__ __forceinline__ float tf32f(float x) {
    unsigned u;
    asm("cvt.rna.tf32.f32 %0, %1;" : "=r"(u) : "f"(x));
    return __uint_as_float(u);
}

// D += A(16x8) * B(8x8), tf32 in, fp32 accumulate
__device__ __forceinline__ void mma8(float c[4], float a0, float a1, float a2, float a3,
                                     float b0, float b1) {
    unsigned A0 = __float_as_uint(a0), A1 = __float_as_uint(a1);
    unsigned A2 = __float_as_uint(a2), A3 = __float_as_uint(a3);
    unsigned B0 = __float_as_uint(b0), B1 = __float_as_uint(b1);
    asm volatile(
        "mma.sync.aligned.m16n8k8.row.col.f32.tf32.tf32.f32 "
        "{%0,%1,%2,%3}, {%4,%5,%6,%7}, {%8,%9}, {%0,%1,%2,%3};\n"
        : "+f"(c[0]), "+f"(c[1]), "+f"(c[2]), "+f"(c[3])
        : "r"(A0), "r"(A1), "r"(A2), "r"(A3), "r"(B0), "r"(B1));
}

// ---------------- gate kernel -------------------------------------------------
__global__ void gate_kernel(const float* __restrict__ x,
                            const float* __restrict__ Wg,
                            const float* __restrict__ bg,
                            const float* __restrict__ grep,
                            float* __restrict__ g1)
{
    __shared__ float wA[HD_], wB[HD_], bsum[2];
    int tid = threadIdx.x;
    if (tid < HD_) {
        float sa = 0.f, sb = 0.f;
        #pragma unroll
        for (int j = 0; j < 4; j++) sa += Wg[tid*8 + j];
        #pragma unroll
        for (int j = 4; j < 8; j++) sb += Wg[tid*8 + j];
        wA[tid] = sa; wB[tid] = sb;
    }
    if (tid == 0) {
        bsum[0] = bg[0]+bg[1]+bg[2]+bg[3];
        bsum[1] = bg[4]+bg[5]+bg[6]+bg[7];
    }
    __syncthreads();

    int idx = blockIdx.x * blockDim.x + tid;    // idx = (b*T + t)*H + h
    if (idx >= BT_*H_) return;
    const float* xp = x + (size_t)idx * HD_;
    float sa = bsum[0], sb = bsum[1];
    #pragma unroll 8
    for (int d = 0; d < HD_; d++) {
        float xv = xp[d];
        sa += xv * wA[d];
        sb += xv * wB[d];
    }
    float a  = 1.f / (1.f + __expf(-sa));
    float bb = 1.f / (1.f + __expf(-sb));
    int h = idx % H_;
    int t = (idx / H_) % T_;
    int b = idx / (H_ * T_);
    g1[(b*H_ + h)*T_ + t] = a * (bb * grep[h] - 1.0f) + 2.0f;
}

// ---------------- TF32 MMA GEMM: C = A(Mx768) @ W(768x768) + bias -------------
// BM=128 BN=128 BK=32, 256 threads (8 warps, 2x4), warp tile 64x32.
__global__ __launch_bounds__(256, 2)
void gemm_tf32(const float* __restrict__ A,
               const float* __restrict__ W,
               const float* __restrict__ bias,
               float* __restrict__ C,
               int remap)
{
    __shared__ float As[32][132];   // [k][m], pad4 -> (4q+g)%32 banks
    __shared__ float Bs[32][132];   // [k][n]

    int tid = threadIdx.x;
    int wid = tid >> 5, lane = tid & 31;
    int g = lane >> 2, ql = lane & 3;
    int wm = wid >> 2, wn = wid & 3;
    int row0 = blockIdx.y * 128, col0 = blockIdx.x * 128;

    float acc[4][4][4] = {};

    int m_a = tid & 127;
    int kqa = (tid >> 7) * 4;       // 0 or 4
    int nb  = (tid & 31) * 4;
    int kb  = tid >> 5;             // 0..7

    for (int kt = 0; kt < 768; kt += 32) {
        #pragma unroll
        for (int c = 0; c < 4; c++) {
            int k = kqa + c*8;
            float4 v = *(const float4*)(A + (size_t)(row0 + m_a)*768 + kt + k);
            As[k+0][m_a] = tf32f(v.x);
            As[k+1][m_a] = tf32f(v.y);
            As[k+2][m_a] = tf32f(v.z);
            As[k+3][m_a] = tf32f(v.w);
        }
        #pragma unroll
        for (int c = 0; c < 4; c++) {
            int k = kb + c*8;
            float4 v = *(const float4*)(W + (size_t)(kt + k)*768 + col0 + nb);
            float4 t;
            t.x = tf32f(v.x); t.y = tf32f(v.y); t.z = tf32f(v.z); t.w = tf32f(v.w);
            *(float4*)&Bs[k][nb] = t;
        }
        __syncthreads();

        #pragma unroll
        for (int ks = 0; ks < 4; ks++) {
            int k0 = ks * 8;
            float b0[4], b1[4];
            #pragma unroll
            for (int j = 0; j < 4; j++) {
                int n = wn*32 + j*8 + g;
                b0[j] = Bs[k0 + ql][n];
                b1[j] = Bs[k0 + ql + 4][n];
            }
            #pragma unroll
            for (int i = 0; i < 4; i++) {
                int m = wm*64 + i*16 + g;
                float a0 = As[k0 + ql][m],     a1 = As[k0 + ql][m + 8];
                float a2 = As[k0 + ql + 4][m], a3 = As[k0 + ql + 4][m + 8];
                #pragma unroll
                for (int j = 0; j < 4; j++)
                    mma8(acc[i][j], a0, a1, a2, a3, b0[j], b1[j]);
            }
        }
        __syncthreads();
    }

    // epilogue
    #pragma unroll
    for (int i = 0; i < 4; i++) {
        #pragma unroll
        for (int j = 0; j < 4; j++) {
            int mrow = row0 + wm*64 + i*16 + g;
            int ncol = col0 + wn*32 + j*8 + 2*ql;
            float bx = bias[ncol], by = bias[ncol + 1];
            #pragma unroll
            for (int rr = 0; rr < 2; rr++) {
                int m = mrow + rr*8;
                float2 val = make_float2(acc[i][j][2*rr] + bx, acc[i][j][2*rr+1] + by);
                int b = m >> 10;
                int t = m & (T_ - 1);
                if (remap) {
                    int h = ncol >> 6;
                    int d = ncol & 63;
                    *(float2*)&C[(((size_t)b*H_ + h)*T_ + t)*HD_ + d] = val;
                } else {
                    *(float2*)&C[(size_t)m * 768 + ncol] = val;
                }
            }
        }
    }
}

// ---------------- flash attention (tf32 mma) ----------------------------------
// Bq=64, Bk=64, 4 warps (128 thr), each warp owns 16 q-rows.
#define QS 0
#define KS (64*68)
#define VS (2*64*68)
#define PS (3*64*68)
#define MSOFF (4*64*68)
__global__ __launch_bounds__(128, 2)
void flash_kernel(const float* __restrict__ q,
                  const float* __restrict__ k,
                  const float* __restrict__ v,
                  const float* __restrict__ rel,
                  const float* __restrict__ mask,
                  const float* __restrict__ g1,
                  float* __restrict__ o)
{
    extern __shared__ float sm[];
    int bh = blockIdx.y;
    int b  = bh / H_;
    int h  = bh % H_;
    int q0 = blockIdx.x * 64;
    int tid  = threadIdx.x;
    int w    = tid >> 5;
    int lane = tid & 31;
    int g  = lane >> 2, ql = lane & 3;
    int r0 = w*16 + g;          // row 0 of this thread
    int r1 = r0 + 8;            // row 1

    const float* qptr  = q + ((size_t)bh * T_ + q0) * HD_;
    const float* kbase = k + (size_t)bh * T_ * HD_;
    const float* vbase = v + (size_t)bh * T_ * HD_;
    const float* rbase = rel + (size_t)bh * T_ * T_;

    // stage Q (tf32-converted), row-major [q][68]
    for (int i = tid; i < 64*16; i += 128) {
        int r = i >> 4, c4 = (i & 15) * 4;
        float4 vv = *(const float4*)&qptr[(size_t)r*HD_ + c4];
        float4 t;
        t.x = tf32f(vv.x); t.y = tf32f(vv.y); t.z = tf32f(vv.z); t.w = tf32f(vv.w);
        *(float4*)&sm[QS + r*68 + c4] = t;
    }
    float ga0 = g1[(size_t)bh*T_ + q0 + r0];
    float ga1 = g1[(size_t)bh*T_ + q0 + r1];

    float m0 = -1e30f, m1 = -1e30f, l0 = 0.f, l1 = 0.f;
    float ov[8][4] = {};

    for (int kt = 0; kt < T_; kt += 64) {
        __syncthreads();
        for (int i = tid; i < 64*16; i += 128) {
            int r = i >> 4, c4 = (i & 15) * 4;
            float4 vv = *(const float4*)&kbase[(size_t)(kt + r)*HD_ + c4];
            float4 t;
            t.x = tf32f(vv.x); t.y = tf32f(vv.y); t.z = tf32f(vv.z); t.w = tf32f(vv.w);
            *(float4*)&sm[KS + r*68 + c4] = t;
        }
        for (int i = tid; i < 64*16; i += 128) {
            int r = i >> 4, c4 = (i & 15) * 4;
            float4 vv = *(const float4*)&vbase[(size_t)(kt + r)*HD_ + c4];
            float4 t;
            t.x = tf32f(vv.x); t.y = tf32f(vv.y); t.z = tf32f(vv.z); t.w = tf32f(vv.w);
            *(float4*)&sm[VS + r*68 + c4] = t;
        }
        if (tid < 64) sm[MSOFF + tid] = mask[(size_t)b*T_ + kt + tid];
        __syncthreads();

        // prefetch rel bias fragments straight from global
        float rv[8][4];
        #pragma unroll
        for (int n = 0; n < 8; n++) {
            int c0 = kt + 8*n + 2*ql;
            rv[n][0] = rbase[(size_t)c0      * T_ + q0 + r0];
            rv[n][1] = rbase[(size_t)(c0+1)  * T_ + q0 + r0];
            rv[n][2] = rbase[(size_t)c0      * T_ + q0 + r1];
            rv[n][3] = rbase[(size_t)(c0+1)  * T_ + q0 + r1];
        }

        // ---- S = Q @ K^T (tf32 mma) ----
        float sc[8][4] = {};
        #pragma unroll
        for (int ks = 0; ks < 8; ks++) {
            int k0 = ks * 8;
            float a0 = sm[QS + r0*68 + k0 + ql];
            float a1 = sm[QS + r1*68 + k0 + ql];
            float a2 = sm[QS + r0*68 + k0 + ql + 4];
            float a3 = sm[QS + r1*68 + k0 + ql + 4];
            #pragma unroll
            for (int n = 0; n < 8; n++) {
                float b0 = sm[KS + (8*n + g)*68 + k0 + ql];
                float b1 = sm[KS + (8*n + g)*68 + k0 + ql + 4];
                mma8(sc[n], a0, a1, a2, a3, b0, b1);
            }
        }

        // ---- bias + mask + online softmax ----
        #pragma unroll
        for (int n = 0; n < 8; n++) {
            float mk0 = sm[MSOFF + 8*n + 2*ql];
            float mk1 = sm[MSOFF + 8*n + 2*ql + 1];
            sc[n][0] = sc[n][0]*0.125f + ga0*rv[n][0] + mk0;
            sc[n][1] = sc[n][1]*0.125f + ga0*rv[n][1] + mk1;
            sc[n][2] = sc[n][2]*0.125f + ga1*rv[n][2] + mk0;
            sc[n][3] = sc[n][3]*0.125f + ga1*rv[n][3] + mk1;
        }
        float mt0 = -1e30f, mt1 = -1e30f;
        #pragma unroll
        for (int n = 0; n < 8; n++) {
            mt0 = fmaxf(mt0, fmaxf(sc[n][0], sc[n][1]));
            mt1 = fmaxf(mt1, fmaxf(sc[n][2], sc[n][3]));
        }
        mt0 = fmaxf(mt0, __shfl_xor_sync(0xffffffffu, mt0, 1));
        mt0 = fmaxf(mt0, __shfl_xor_sync(0xffffffffu, mt0, 2));
        mt1 = fmaxf(mt1, __shfl_xor_sync(0xffffffffu, mt1, 1));
        mt1 = fmaxf(mt1, __shfl_xor_sync(0xffffffffu, mt1, 2));
        float mn0 = fmaxf(m0, mt0), mn1 = fmaxf(m1, mt1);
        float al0 = __expf(m0 - mn0), al1 = __expf(m1 - mn1);
        m0 = mn0; m1 = mn1;
        float s0 = 0.f, s1 = 0.f;
        #pragma unroll
        for (int n = 0; n < 8; n++) {
            sc[n][0] = __expf(sc[n][0] - mn0);
            sc[n][1] = __expf(sc[n][1] - mn0);
            sc[n][2] = __expf(sc[n][2] - mn1);
            sc[n][3] = __expf(sc[n][3] - mn1);
            s0 += sc[n][0] + sc[n][1];
            s1 += sc[n][2] + sc[n][3];
        }
        s0 += __shfl_xor_sync(0xffffffffu, s0, 1);
        s0 += __shfl_xor_sync(0xffffffffu, s0, 2);
        s1 += __shfl_xor_sync(0xffffffffu, s1, 1);
        s1 += __shfl_xor_sync(0xffffffffu, s1, 2);
        l0 = l0 * al0 + s0;
        l1 = l1 * al1 + s1;
        #pragma unroll
        for (int n = 0; n < 8; n++) {
            ov[n][0] *= al0; ov[n][1] *= al0;
            ov[n][2] *= al1; ov[n][3] *= al1;
        }

        // ---- store P fragments (tf32) for re-fragmentation ----
        #pragma unroll
        for (int n = 0; n < 8; n++) {
            *(float2*)&sm[PS + r0*68 + 8*n + 2*ql] =
                make_float2(tf32f(sc[n][0]), tf32f(sc[n][1]));
            *(float2*)&sm[PS + r1*68 + 8*n + 2*ql] =
                make_float2(tf32f(sc[n][2]), tf32f(sc[n][3]));
        }
        __syncwarp();

        // ---- O += P @ V (tf32 mma) ----
        #pragma unroll
        for (int ks = 0; ks < 8; ks++) {
            int k0 = ks * 8;
            float a0 = sm[PS + r0*68 + k0 + ql];
            float a1 = sm[PS + r1*68 + k0 + ql];
            float a2 = sm[PS + r0*68 + k0 + ql + 4];
            float a3 = sm[PS + r1*68 + k0 + ql + 4];
            #pragma unroll
            for (int n = 0; n < 8; n++) {
                float b0 = sm[VS + (k0 + ql)*68 + 8*n + g];
                float b1 = sm[VS + (k0 + ql + 4)*68 + 8*n + g];
                mma8(ov[n], a0, a1, a2, a3, b0, b1);
            }
        }
    }

    // epilogue: normalize, merge heads into (B,T,D)
    float inv0 = 1.f / l0, inv1 = 1.f / l1;
    #pragma unroll
    for (int n = 0; n < 8; n++) {
        int d = h*HD_ + 8*n + 2*ql;
        *(float2*)&o[((size_t)b*T_ + q0 + r0)*D_ + d] =
            make_float2(ov[n][0]*inv0, ov[n][1]*inv0);
        *(float2*)&o[((size_t)b*T_ + q0 + r1)*D_ + d] =
            make_float2(ov[n][2]*inv1, ov[n][3]*inv1);
    }
}

// ---------------- launch ------------------------------------------------------
extern "C" void kernel_launch(void* const* d_in, const int* in_sizes, int n_in,
                              void* d_out, int out_size)
{
    const float* x    = (const float*)d_in[0];
    const float* mask = (const float*)d_in[1];
    const float* rel  = (const float*)d_in[2];
    const float* Wq   = (const float*)d_in[3];
    const float* bq   = (const float*)d_in[4];
    const float* Wk   = (const float*)d_in[5];
    const float* bk   = (const float*)d_in[6];
    const float* Wv   = (const float*)d_in[7];
    const float* bv   = (const float*)d_in[8];
    const float* Wo   = (const float*)d_in[9];
    const float* bo   = (const float*)d_in[10];
    const float* Wg   = (const float*)d_in[11];
    const float* bg   = (const float*)d_in[12];
    const float* grep = (const float*)d_in[13];
    float* out = (float*)d_out;

    float *qb, *kb, *vb, *ob, *g1b;
    cudaGetSymbolAddress((void**)&qb,  g_q);
    cudaGetSymbolAddress((void**)&kb,  g_k);
    cudaGetSymbolAddress((void**)&vb,  g_v);
    cudaGetSymbolAddress((void**)&ob,  g_o);
    cudaGetSymbolAddress((void**)&g1b, g_g1);

    gate_kernel<<<(BT_*H_)/256, 256>>>(x, Wg, bg, grep, g1b);

    dim3 gg(D_/128, BT_/128);   // (6, 64)
    gemm_tf32<<<gg, 256>>>(x, Wq, bq, qb, 1);
    gemm_tf32<<<gg, 256>>>(x, Wk, bk, kb, 1);
    gemm_tf32<<<gg, 256>>>(x, Wv, bv, vb, 1);

    const int SMEM = (4*64*68 + 64) * 4;    // 69888 B
    cudaFuncSetAttribute(flash_kernel, cudaFuncAttributeMaxDynamicSharedMemorySize, SMEM);
    flash_kernel<<<dim3(T_/64, BH_), 128, SMEM>>>(qb, kb, vb, rel, mask, g1b, ob);

    gemm_tf32<<<gg, 256>>>(ob, Wo, bo, out, 0);
}

// round 6
// speedup vs baseline: 2.7320x; 1.3079x over previous
#include <cuda_runtime.h>
#include <cstdint>

#define B_ 8
#define T_ 1024
#define D_ 768
#define H_ 12
#define HD_ 64
#define BT_ (B_*T_)          // 8192
#define BH_ (B_*H_)          // 96

// ---------------- scratch (static device globals; no allocation) --------------
__device__ float g_q[BT_*D_];
__device__ float g_k[BT_*D_];
__device__ float g_v[BT_*D_];
__device__ float g_o[BT_*D_];
__device__ float g_xr[BT_*D_];
__device__ float g_w[4][D_*D_];
__device__ float g_g1[BH_*T_];

// ---------------- helpers -----------------------------------------------------
__device__ __forceinline__ float tf32f(float x) {
    unsigned u;
    asm("cvt.rna.tf32.f32 %0, %1;" : "=r"(u) : "f"(x));
    return __uint_as_float(u);
}
__device__ __forceinline__ unsigned sptr(const void* p) {
    return (unsigned)__cvta_generic_to_shared(p);
}
__device__ __forceinline__ void cp16(unsigned s, const void* g) {
    asm volatile("cp.async.cg.shared.global [%0], [%1], 16;\n" :: "r"(s), "l"(g));
}
__device__ __forceinline__ void cp_commit() {
    asm volatile("cp.async.commit_group;\n");
}
__device__ __forceinline__ void ldsm4(unsigned& r0, unsigned& r1, unsigned& r2, unsigned& r3,
                                      unsigned addr) {
    asm volatile("ldmatrix.sync.aligned.m8n8.x4.shared.b16 {%0,%1,%2,%3}, [%4];\n"
                 : "=r"(r0), "=r"(r1), "=r"(r2), "=r"(r3) : "r"(addr));
}
__device__ __forceinline__ void mma8u(float c[4], unsigned A0, unsigned A1, unsigned A2,
                                      unsigned A3, unsigned B0, unsigned B1) {
    asm volatile(
        "mma.sync.aligned.m16n8k8.row.col.f32.tf32.tf32.f32 "
        "{%0,%1,%2,%3}, {%4,%5,%6,%7}, {%8,%9}, {%0,%1,%2,%3};\n"
        : "+f"(c[0]), "+f"(c[1]), "+f"(c[2]), "+f"(c[3])
        : "r"(A0), "r"(A1), "r"(A2), "r"(A3), "r"(B0), "r"(B1));
}

// ---------------- tf32 pre-rounding -------------------------------------------
__global__ void round_kernel(const float* __restrict__ in, float* __restrict__ out, int n4) {
    int i = blockIdx.x * blockDim.x + threadIdx.x;
    if (i >= n4) return;
    float4 v = ((const float4*)in)[i];
    v.x = tf32f(v.x); v.y = tf32f(v.y); v.z = tf32f(v.z); v.w = tf32f(v.w);
    ((float4*)out)[i] = v;
}

// ---------------- gate kernel -------------------------------------------------
__global__ void gate_kernel(const float* __restrict__ x,
                            const float* __restrict__ Wg,
                            const float* __restrict__ bg,
                            const float* __restrict__ grep,
                            float* __restrict__ g1)
{
    __shared__ float wA[HD_], wB[HD_], bsum[2];
    int tid = threadIdx.x;
    if (tid < HD_) {
        float sa = 0.f, sb = 0.f;
        #pragma unroll
        for (int j = 0; j < 4; j++) sa += Wg[tid*8 + j];
        #pragma unroll
        for (int j = 4; j < 8; j++) sb += Wg[tid*8 + j];
        wA[tid] = sa; wB[tid] = sb;
    }
    if (tid == 0) {
        bsum[0] = bg[0]+bg[1]+bg[2]+bg[3];
        bsum[1] = bg[4]+bg[5]+bg[6]+bg[7];
    }
    __syncthreads();

    int idx = blockIdx.x * blockDim.x + tid;
    if (idx >= BT_*H_) return;
    const float* xp = x + (size_t)idx * HD_;
    float sa = bsum[0], sb = bsum[1];
    #pragma unroll 8
    for (int d = 0; d < HD_; d++) {
        float xv = xp[d];
        sa += xv * wA[d];
        sb += xv * wB[d];
    }
    float a  = 1.f / (1.f + __expf(-sa));
    float bb = 1.f / (1.f + __expf(-sb));
    int h = idx % H_;
    int t = (idx / H_) % T_;
    int b = idx / (H_ * T_);
    g1[(b*H_ + h)*T_ + t] = a * (bb * grep[h] - 1.0f) + 2.0f;
}

// ---------------- TF32 MMA GEMM (cp.async double-buffer + ldmatrix A) ---------
// C = A(8192x768) @ W(768x768) + bias. BM=128 BN=128 BK=32, 256 thr, warp 64x32.
// A,W must be tf32-pre-rounded. remap=1 -> head-split layout + round output.
#define AS_STAGE (128*32)          // floats per A stage
#define BS_STAGE (32*132)          // floats per B stage
__global__ __launch_bounds__(256, 2)
void gemm_tf32(const float* __restrict__ A,
               const float* __restrict__ W,
               const float* __restrict__ bias,
               float* __restrict__ C,
               int remap)
{
    extern __shared__ float sm[];
    float* Bs = sm + 2*AS_STAGE;

    int tid = threadIdx.x;
    int wid = tid >> 5, lane = tid & 31;
    int g = lane >> 2, ql = lane & 3;
    int wm = wid >> 2, wn = wid & 3;
    int row0 = blockIdx.y * 128, col0 = blockIdx.x * 128;

    // staging assignments
    int m_a   = tid >> 1;
    int cbase = (tid & 1) * 4;
    const float* Agp = A + (size_t)(row0 + m_a)*768 + cbase*4;
    unsigned As_s = sptr(sm) + (m_a*32)*4;     // byte base of row m_a

    int kb = tid >> 3;                // 0..31
    int cb = (tid & 7) * 4;           // chunk col base
    const float* Wgp = W + (size_t)kb*768 + col0 + cb*4;
    unsigned Bs_s = sptr(Bs) + (kb*132 + cb*4)*4;

    // ldmatrix lane addressing for A
    int rlA = ((lane >> 3) & 1)*8 + (lane & 7);
    int hA  = lane >> 4;
    int swzA = lane & 7;
    unsigned aoff[4];
    #pragma unroll
    for (int i = 0; i < 4; i++)
        aoff[i] = sptr(sm) + ((wm*64 + i*16 + rlA)*32)*4;

    float acc[4][4][4] = {};

    // prefetch stage 0
    #pragma unroll
    for (int c = 0; c < 4; c++)
        cp16(As_s + (((cbase + c) ^ (m_a & 7))*4)*4, Agp + c*4);
    #pragma unroll
    for (int c = 0; c < 4; c++)
        cp16(Bs_s + c*16, Wgp + c*4);
    cp_commit();

    for (int kt = 0; kt < 24; kt++) {
        int cur = kt & 1;
        if (kt < 23) {
            int nxt = cur ^ 1;
            const float* Ag = Agp + (kt+1)*32;
            const float* Wg2 = Wgp + (size_t)(kt+1)*32*768;
            #pragma unroll
            for (int c = 0; c < 4; c++)
                cp16(As_s + (nxt*AS_STAGE)*4 + (((cbase + c) ^ (m_a & 7))*4)*4, Ag + c*4);
            #pragma unroll
            for (int c = 0; c < 4; c++)
                cp16(Bs_s + (nxt*BS_STAGE)*4 + c*16, Wg2 + c*4);
            cp_commit();
            asm volatile("cp.async.wait_group 1;\n");
        } else {
            asm volatile("cp.async.wait_group 0;\n");
        }
        __syncthreads();

        const float* Bc = Bs + cur*BS_STAGE;
        unsigned abase = cur*AS_STAGE*4;
        #pragma unroll
        for (int ks = 0; ks < 4; ks++) {
            unsigned ccol = (unsigned)(((2*ks + hA) ^ swzA) * 16);
            unsigned af[4][4];
            #pragma unroll
            for (int i = 0; i < 4; i++)
                ldsm4(af[i][0], af[i][1], af[i][2], af[i][3], aoff[i] + abase + ccol);
            int k0 = ks*8;
            unsigned b0[4], b1[4];
            #pragma unroll
            for (int j = 0; j < 4; j++) {
                int n = wn*32 + j*8 + g;
                b0[j] = __float_as_uint(Bc[(k0 + ql)*132 + n]);
                b1[j] = __float_as_uint(Bc[(k0 + ql + 4)*132 + n]);
            }
            #pragma unroll
            for (int i = 0; i < 4; i++)
                #pragma unroll
                for (int j = 0; j < 4; j++)
                    mma8u(acc[i][j], af[i][0], af[i][1], af[i][2], af[i][3], b0[j], b1[j]);
        }
        __syncthreads();
    }

    // epilogue
    #pragma unroll
    for (int i = 0; i < 4; i++) {
        #pragma unroll
        for (int j = 0; j < 4; j++) {
            int mrow = row0 + wm*64 + i*16 + g;
            int ncol = col0 + wn*32 + j*8 + 2*ql;
            float bx = bias[ncol], by = bias[ncol + 1];
            #pragma unroll
            for (int rr = 0; rr < 2; rr++) {
                int m = mrow + rr*8;
                float2 val = make_float2(acc[i][j][2*rr] + bx, acc[i][j][2*rr+1] + by);
                int b = m >> 10;
                int t = m & (T_ - 1);
                if (remap) {
                    val.x = tf32f(val.x); val.y = tf32f(val.y);
                    int h = ncol >> 6;
                    int d = ncol & 63;
                    *(float2*)&C[(((size_t)b*H_ + h)*T_ + t)*HD_ + d] = val;
                } else {
                    *(float2*)&C[(size_t)m * 768 + ncol] = val;
                }
            }
        }
    }
}

// ---------------- flash attention (tf32 mma + ldmatrix) -----------------------
// Bq=64, Bk=64, 4 warps; warp owns 16 q-rows. q/k/v pre-rounded tf32.
#define FQ 0
#define FK (64*68)
#define FV (2*64*68)
#define FP (3*64*68)
#define FM (4*64*68)
__global__ __launch_bounds__(128, 2)
void flash_kernel(const float* __restrict__ q,
                  const float* __restrict__ k,
                  const float* __restrict__ v,
                  const float* __restrict__ rel,
                  const float* __restrict__ mask,
                  const float* __restrict__ g1,
                  float* __restrict__ o)
{
    extern __shared__ float sm[];
    int bh = blockIdx.y;
    int b  = bh / H_;
    int h  = bh % H_;
    int q0 = blockIdx.x * 64;
    int tid  = threadIdx.x;
    int w    = tid >> 5;
    int lane = tid & 31;
    int g  = lane >> 2, ql = lane & 3;
    int r0 = w*16 + g;
    int r1 = r0 + 8;

    const float* qptr  = q + ((size_t)bh * T_ + q0) * HD_;
    const float* kbase = k + (size_t)bh * T_ * HD_;
    const float* vbase = v + (size_t)bh * T_ * HD_;
    const float* rbase = rel + (size_t)bh * T_ * T_;

    unsigned smb = sptr(sm);

    // ldmatrix lane addressing
    int rlA = ((lane >> 3) & 1)*8 + (lane & 7);
    int hA  = lane >> 4;
    int rlB = ((lane >> 4) & 1)*8 + (lane & 7);
    int hB  = (lane >> 3) & 1;
    unsigned qAoff = smb + (FQ + (w*16 + rlA)*68)*4;
    unsigned pAoff = smb + (FP + (w*16 + rlA)*68)*4;
    unsigned kBoff[4], vBoff[4];
    #pragma unroll
    for (int jj = 0; jj < 4; jj++) {
        kBoff[jj] = smb + (FK + (jj*16 + rlB)*68)*4;
        vBoff[jj] = smb + (FV + (jj*16 + rlB)*68)*4;
    }

    // stage Q via cp.async: 64 rows x 16 chunks = 1024 chunks, 8 per thread
    #pragma unroll
    for (int i = 0; i < 8; i++) {
        int j = tid + 128*i;
        int r = j >> 4, c = j & 15;
        cp16(smb + (FQ + r*68 + c*4)*4, qptr + (size_t)r*HD_ + c*4);
    }
    cp_commit();

    float ga0 = g1[(size_t)bh*T_ + q0 + r0];
    float ga1 = g1[(size_t)bh*T_ + q0 + r1];

    float m0 = -1e30f, m1 = -1e30f, l0 = 0.f, l1 = 0.f;
    float ov[8][4] = {};

    for (int kt = 0; kt < T_; kt += 64) {
        __syncthreads();
        // K tile via cp.async: full 64x64 tile
        #pragma unroll
        for (int i = 0; i < 8; i++) {
            int j = tid + 128*i;
            int r = j >> 4, c = j & 15;
            cp16(smb + (FK + r*68 + c*4)*4, kbase + (size_t)(kt + r)*HD_ + c*4);
        }
        cp_commit();
        // V tile transposed: Vt[d][kseq]
        #pragma unroll
        for (int it = 0; it < 8; it++) {
            int idx = tid + 128*it;
            int r = idx >> 4;            // kseq
            int c4 = (idx & 15) * 4;     // d
            float4 vv = *(const float4*)&vbase[(size_t)(kt + r)*HD_ + c4];
            sm[FV + (c4+0)*68 + r] = vv.x;
            sm[FV + (c4+1)*68 + r] = vv.y;
            sm[FV + (c4+2)*68 + r] = vv.z;
            sm[FV + (c4+3)*68 + r] = vv.w;
        }
        if (tid < 64) sm[FM + tid] = mask[(size_t)b*T_ + kt + tid];

        // rel bias fragments direct from global (overlaps cp.async)
        float rv[8][4];
        #pragma unroll
        for (int n = 0; n < 8; n++) {
            int c0 = kt + 8*n + 2*ql;
            rv[n][0] = rbase[(size_t)c0      * T_ + q0 + r0];
            rv[n][1] = rbase[(size_t)(c0+1)  * T_ + q0 + r0];
            rv[n][2] = rbase[(size_t)c0      * T_ + q0 + r1];
            rv[n][3] = rbase[(size_t)(c0+1)  * T_ + q0 + r1];
        }
        asm volatile("cp.async.wait_group 0;\n");
        __syncthreads();

        // ---- S = Q @ K^T ----
        float sc[8][4] = {};
        #pragma unroll
        for (int ks = 0; ks < 8; ks++) {
            unsigned ca  = (unsigned)((2*ks + hA)*16);
            unsigned cbk = (unsigned)((2*ks + hB)*16);
            unsigned qa0, qa1, qa2, qa3;
            ldsm4(qa0, qa1, qa2, qa3, qAoff + ca);
            #pragma unroll
            for (int jj = 0; jj < 4; jj++) {
                unsigned kb0, kb1, kb2, kb3;
                ldsm4(kb0, kb1, kb2, kb3, kBoff[jj] + cbk);
                mma8u(sc[2*jj],   qa0, qa1, qa2, qa3, kb0, kb1);
                mma8u(sc[2*jj+1], qa0, qa1, qa2, qa3, kb2, kb3);
            }
        }

        // ---- bias + mask + online softmax ----
        #pragma unroll
        for (int n = 0; n < 8; n++) {
            float mk0 = sm[FM + 8*n + 2*ql];
            float mk1 = sm[FM + 8*n + 2*ql + 1];
            sc[n][0] = sc[n][0]*0.125f + ga0*rv[n][0] + mk0;
            sc[n][1] = sc[n][1]*0.125f + ga0*rv[n][1] + mk1;
            sc[n][2] = sc[n][2]*0.125f + ga1*rv[n][2] + mk0;
            sc[n][3] = sc[n][3]*0.125f + ga1*rv[n][3] + mk1;
        }
        float mt0 = -1e30f, mt1 = -1e30f;
        #pragma unroll
        for (int n = 0; n < 8; n++) {
            mt0 = fmaxf(mt0, fmaxf(sc[n][0], sc[n][1]));
            mt1 = fmaxf(mt1, fmaxf(sc[n][2], sc[n][3]));
        }
        mt0 = fmaxf(mt0, __shfl_xor_sync(0xffffffffu, mt0, 1));
        mt0 = fmaxf(mt0, __shfl_xor_sync(0xffffffffu, mt0, 2));
        mt1 = fmaxf(mt1, __shfl_xor_sync(0xffffffffu, mt1, 1));
        mt1 = fmaxf(mt1, __shfl_xor_sync(0xffffffffu, mt1, 2));
        float mn0 = fmaxf(m0, mt0), mn1 = fmaxf(m1, mt1);
        float al0 = __expf(m0 - mn0), al1 = __expf(m1 - mn1);
        m0 = mn0; m1 = mn1;
        float s0 = 0.f, s1 = 0.f;
        #pragma unroll
        for (int n = 0; n < 8; n++) {
            sc[n][0] = __expf(sc[n][0] - mn0);
            sc[n][1] = __expf(sc[n][1] - mn0);
            sc[n][2] = __expf(sc[n][2] - mn1);
            sc[n][3] = __expf(sc[n][3] - mn1);
            s0 += sc[n][0] + sc[n][1];
            s1 += sc[n][2] + sc[n][3];
        }
        s0 += __shfl_xor_sync(0xffffffffu, s0, 1);
        s0 += __shfl_xor_sync(0xffffffffu, s0, 2);
        s1 += __shfl_xor_sync(0xffffffffu, s1, 1);
        s1 += __shfl_xor_sync(0xffffffffu, s1, 2);
        l0 = l0 * al0 + s0;
        l1 = l1 * al1 + s1;
        #pragma unroll
        for (int n = 0; n < 8; n++) {
            ov[n][0] *= al0; ov[n][1] *= al0;
            ov[n][2] *= al1; ov[n][3] *= al1;
        }

        // ---- store P (tf32-rounded) ----
        #pragma unroll
        for (int n = 0; n < 8; n++) {
            *(float2*)&sm[FP + r0*68 + 8*n + 2*ql] =
                make_float2(tf32f(sc[n][0]), tf32f(sc[n][1]));
            *(float2*)&sm[FP + r1*68 + 8*n + 2*ql] =
                make_float2(tf32f(sc[n][2]), tf32f(sc[n][3]));
        }
        __syncwarp();

        // ---- O += P @ V ----
        #pragma unroll
        for (int ks = 0; ks < 8; ks++) {
            unsigned ca  = (unsigned)((2*ks + hA)*16);
            unsigned cbv = (unsigned)((2*ks + hB)*16);
            unsigned pa0, pa1, pa2, pa3;
            ldsm4(pa0, pa1, pa2, pa3, pAoff + ca);
            #pragma unroll
            for (int jj = 0; jj < 4; jj++) {
                unsigned vb0, vb1, vb2, vb3;
                ldsm4(vb0, vb1, vb2, vb3, vBoff[jj] + cbv);
                mma8u(ov[2*jj],   pa0, pa1, pa2, pa3, vb0, vb1);
                mma8u(ov[2*jj+1], pa0, pa1, pa2, pa3, vb2, vb3);
            }
        }
    }

    // epilogue: normalize, tf32-round (feeds final GEMM), merge heads
    float inv0 = 1.f / l0, inv1 = 1.f / l1;
    #pragma unroll
    for (int n = 0; n < 8; n++) {
        int d = h*HD_ + 8*n + 2*ql;
        *(float2*)&o[((size_t)b*T_ + q0 + r0)*D_ + d] =
            make_float2(tf32f(ov[n][0]*inv0), tf32f(ov[n][1]*inv0));
        *(float2*)&o[((size_t)b*T_ + q0 + r1)*D_ + d] =
            make_float2(tf32f(ov[n][2]*inv1), tf32f(ov[n][3]*inv1));
    }
}

// ---------------- launch ------------------------------------------------------
extern "C" void kernel_launch(void* const* d_in, const int* in_sizes, int n_in,
                              void* d_out, int out_size)
{
    const float* x    = (const float*)d_in[0];
    const float* mask = (const float*)d_in[1];
    const float* rel  = (const float*)d_in[2];
    const float* Wq   = (const float*)d_in[3];
    const float* bq   = (const float*)d_in[4];
    const float* Wk   = (const float*)d_in[5];
    const float* bk   = (const float*)d_in[6];
    const float* Wv   = (const float*)d_in[7];
    const float* bv   = (const float*)d_in[8];
    const float* Wo   = (const float*)d_in[9];
    const float* bo   = (const float*)d_in[10];
    const float* Wg   = (const float*)d_in[11];
    const float* bg   = (const float*)d_in[12];
    const float* grep = (const float*)d_in[13];
    float* out = (float*)d_out;

    float *qb, *kb, *vb, *ob, *xr, *wr, *g1b;
    cudaGetSymbolAddress((void**)&qb,  g_q);
    cudaGetSymbolAddress((void**)&kb,  g_k);
    cudaGetSymbolAddress((void**)&vb,  g_v);
    cudaGetSymbolAddress((void**)&ob,  g_o);
    cudaGetSymbolAddress((void**)&xr,  g_xr);
    cudaGetSymbolAddress((void**)&wr,  g_w);
    cudaGetSymbolAddress((void**)&g1b, g_g1);

    // pre-round x and weights to tf32
    round_kernel<<<(BT_*D_/4 + 255)/256, 256>>>(x,  xr, BT_*D_/4);
    round_kernel<<<(D_*D_/4 + 255)/256, 256>>>(Wq, wr + 0*D_*D_, D_*D_/4);
    round_kernel<<<(D_*D_/4 + 255)/256, 256>>>(Wk, wr + 1*D_*D_, D_*D_/4);
    round_kernel<<<(D_*D_/4 + 255)/256, 256>>>(Wv, wr + 2*D_*D_, D_*D_/4);
    round_kernel<<<(D_*D_/4 + 255)/256, 256>>>(Wo, wr + 3*D_*D_, D_*D_/4);

    gate_kernel<<<(BT_*H_)/256, 256>>>(x, Wg, bg, grep, g1b);

    const int GSMEM = (2*AS_STAGE + 2*BS_STAGE) * 4;   // 66560 B
    cudaFuncSetAttribute(gemm_tf32, cudaFuncAttributeMaxDynamicSharedMemorySize, GSMEM);
    dim3 gg(D_/128, BT_/128);   // (6, 64)
    gemm_tf32<<<gg, 256, GSMEM>>>(xr, wr + 0*D_*D_, bq, qb, 1);
    gemm_tf32<<<gg, 256, GSMEM>>>(xr, wr + 1*D_*D_, bk, kb, 1);
    gemm_tf32<<<gg, 256, GSMEM>>>(xr, wr + 2*D_*D_, bv, vb, 1);

    const int FSMEM = (4*64*68 + 64) * 4;    // 69888 B
    cudaFuncSetAttribute(flash_kernel, cudaFuncAttributeMaxDynamicSharedMemorySize, FSMEM);
    flash_kernel<<<dim3(T_/64, BH_), 128, FSMEM>>>(qb, kb, vb, rel, mask, g1b, ob);

    gemm_tf32<<<gg, 256, GSMEM>>>(ob, wr + 3*D_*D_, bo, out, 0);
}

// round 11
// speedup vs baseline: 2.9575x; 1.0826x over previous
#include <cuda_runtime.h>
#include <cstdint>

#define B_ 8
#define T_ 1024
#define D_ 768
#define H_ 12
#define HD_ 64
#define BT_ (B_*T_)          // 8192
#define BH_ (B_*H_)          // 96

// ---------------- scratch (static device globals; no allocation) --------------
__device__ float g_q[BT_*D_];
__device__ float g_k[BT_*D_];
__device__ float g_v[BT_*D_];
__device__ float g_o[BT_*D_];
__device__ float g_xr[BT_*D_];
__device__ float g_w[4][D_*D_];
__device__ float g_g1[BH_*T_];

// ---------------- helpers -----------------------------------------------------
__device__ __forceinline__ float tf32f(float x) {
    unsigned u;
    asm("cvt.rna.tf32.f32 %0, %1;" : "=r"(u) : "f"(x));
    return __uint_as_float(u);
}
__device__ __forceinline__ unsigned sptr(const void* p) {
    return (unsigned)__cvta_generic_to_shared(p);
}
__device__ __forceinline__ void cp16(unsigned s, const void* g) {
    asm volatile("cp.async.cg.shared.global [%0], [%1], 16;\n" :: "r"(s), "l"(g));
}
__device__ __forceinline__ void cp_commit() {
    asm volatile("cp.async.commit_group;\n");
}
__device__ __forceinline__ void ldsm4(unsigned& r0, unsigned& r1, unsigned& r2, unsigned& r3,
                                      unsigned addr) {
    asm volatile("ldmatrix.sync.aligned.m8n8.x4.shared.b16 {%0,%1,%2,%3}, [%4];\n"
                 : "=r"(r0), "=r"(r1), "=r"(r2), "=r"(r3) : "r"(addr));
}
__device__ __forceinline__ void mma8u(float c[4], unsigned A0, unsigned A1, unsigned A2,
                                      unsigned A3, unsigned B0, unsigned B1) {
    asm volatile(
        "mma.sync.aligned.m16n8k8.row.col.f32.tf32.tf32.f32 "
        "{%0,%1,%2,%3}, {%4,%5,%6,%7}, {%8,%9}, {%0,%1,%2,%3};\n"
        : "+f"(c[0]), "+f"(c[1]), "+f"(c[2]), "+f"(c[3])
        : "r"(A0), "r"(A1), "r"(A2), "r"(A3), "r"(B0), "r"(B1));
}

// ---------------- tf32 pre-rounding -------------------------------------------
__global__ void round_kernel(const float* __restrict__ in, float* __restrict__ out, int n4) {
    int i = blockIdx.x * blockDim.x + threadIdx.x;
    if (i >= n4) return;
    float4 v = ((const float4*)in)[i];
    v.x = tf32f(v.x); v.y = tf32f(v.y); v.z = tf32f(v.z); v.w = tf32f(v.w);
    ((float4*)out)[i] = v;
}

// ---------------- gate kernel -------------------------------------------------
__global__ void gate_kernel(const float* __restrict__ x,
                            const float* __restrict__ Wg,
                            const float* __restrict__ bg,
                            const float* __restrict__ grep,
                            float* __restrict__ g1)
{
    __shared__ float wA[HD_], wB[HD_], bsum[2];
    int tid = threadIdx.x;
    if (tid < HD_) {
        float sa = 0.f, sb = 0.f;
        #pragma unroll
        for (int j = 0; j < 4; j++) sa += Wg[tid*8 + j];
        #pragma unroll
        for (int j = 4; j < 8; j++) sb += Wg[tid*8 + j];
        wA[tid] = sa; wB[tid] = sb;
    }
    if (tid == 0) {
        bsum[0] = bg[0]+bg[1]+bg[2]+bg[3];
        bsum[1] = bg[4]+bg[5]+bg[6]+bg[7];
    }
    __syncthreads();

    int idx = blockIdx.x * blockDim.x + tid;
    if (idx >= BT_*H_) return;
    const float* xp = x + (size_t)idx * HD_;
    float sa = bsum[0], sb = bsum[1];
    #pragma unroll 8
    for (int d = 0; d < HD_; d++) {
        float xv = xp[d];
        sa += xv * wA[d];
        sb += xv * wB[d];
    }
    float a  = 1.f / (1.f + __expf(-sa));
    float bb = 1.f / (1.f + __expf(-sb));
    int h = idx % H_;
    int t = (idx / H_) % T_;
    int b = idx / (H_ * T_);
    g1[(b*H_ + h)*T_ + t] = a * (bb * grep[h] - 1.0f) + 2.0f;
}

// ---------------- TF32 MMA GEMM (cp.async double-buffer + ldmatrix A) ---------
// grid.z selects (W, bias, C). C = A(8192x768) @ W(768x768) + bias.
// BM=128 BN=128 BK=32, 256 thr, warp 64x32. A,W tf32-pre-rounded.
#define AS_STAGE (128*32)          // floats per A stage
#define BS_STAGE (32*132)          // floats per B stage
__global__ __launch_bounds__(256, 2)
void gemm_tf32(const float* __restrict__ A,
               const float* __restrict__ Wbase,
               const float* __restrict__ bias0,
               const float* __restrict__ bias1,
               const float* __restrict__ bias2,
               float* __restrict__ C0,
               float* __restrict__ C1,
               float* __restrict__ C2,
               int remap)
{
    extern __shared__ float sm[];
    float* Bs = sm + 2*AS_STAGE;

    int z = blockIdx.z;
    const float* W    = Wbase + (size_t)z * D_ * D_;
    const float* bias = (z == 0) ? bias0 : (z == 1) ? bias1 : bias2;
    float*       C    = (z == 0) ? C0    : (z == 1) ? C1    : C2;

    int tid = threadIdx.x;
    int wid = tid >> 5, lane = tid & 31;
    int g = lane >> 2, ql = lane & 3;
    int wm = wid >> 2, wn = wid & 3;
    int row0 = blockIdx.y * 128, col0 = blockIdx.x * 128;

    // staging assignments
    int m_a   = tid >> 1;
    int cbase = (tid & 1) * 4;
    const float* Agp = A + (size_t)(row0 + m_a)*768 + cbase*4;
    unsigned As_s = sptr(sm) + (m_a*32)*4;     // byte base of row m_a

    int kb = tid >> 3;                // 0..31
    int cb = (tid & 7) * 4;           // chunk col base
    const float* Wgp = W + (size_t)kb*768 + col0 + cb*4;
    unsigned Bs_s = sptr(Bs) + (kb*132 + cb*4)*4;

    // ldmatrix lane addressing for A
    int rlA = ((lane >> 3) & 1)*8 + (lane & 7);
    int hA  = lane >> 4;
    int swzA = lane & 7;
    unsigned aoff[4];
    #pragma unroll
    for (int i = 0; i < 4; i++)
        aoff[i] = sptr(sm) + ((wm*64 + i*16 + rlA)*32)*4;

    float acc[4][4][4] = {};

    // prefetch stage 0
    #pragma unroll
    for (int c = 0; c < 4; c++)
        cp16(As_s + (((cbase + c) ^ (m_a & 7))*4)*4, Agp + c*4);
    #pragma unroll
    for (int c = 0; c < 4; c++)
        cp16(Bs_s + c*16, Wgp + c*4);
    cp_commit();

    for (int kt = 0; kt < 24; kt++) {
        int cur = kt & 1;
        if (kt < 23) {
            int nxt = cur ^ 1;
            const float* Ag = Agp + (kt+1)*32;
            const float* Wg2 = Wgp + (size_t)(kt+1)*32*768;
            #pragma unroll
            for (int c = 0; c < 4; c++)
                cp16(As_s + (nxt*AS_STAGE)*4 + (((cbase + c) ^ (m_a & 7))*4)*4, Ag + c*4);
            #pragma unroll
            for (int c = 0; c < 4; c++)
                cp16(Bs_s + (nxt*BS_STAGE)*4 + c*16, Wg2 + c*4);
            cp_commit();
            asm volatile("cp.async.wait_group 1;\n");
        } else {
            asm volatile("cp.async.wait_group 0;\n");
        }
        __syncthreads();

        const float* Bc = Bs + cur*BS_STAGE;
        unsigned abase = cur*AS_STAGE*4;
        #pragma unroll
        for (int ks = 0; ks < 4; ks++) {
            unsigned ccol = (unsigned)(((2*ks + hA) ^ swzA) * 16);
            unsigned af[4][4];
            #pragma unroll
            for (int i = 0; i < 4; i++)
                ldsm4(af[i][0], af[i][1], af[i][2], af[i][3], aoff[i] + abase + ccol);
            int k0 = ks*8;
            unsigned b0[4], b1[4];
            #pragma unroll
            for (int j = 0; j < 4; j++) {
                int n = wn*32 + j*8 + g;
                b0[j] = __float_as_uint(Bc[(k0 + ql)*132 + n]);
                b1[j] = __float_as_uint(Bc[(k0 + ql + 4)*132 + n]);
            }
            #pragma unroll
            for (int i = 0; i < 4; i++)
                #pragma unroll
                for (int j = 0; j < 4; j++)
                    mma8u(acc[i][j], af[i][0], af[i][1], af[i][2], af[i][3], b0[j], b1[j]);
        }
        __syncthreads();
    }

    // epilogue
    #pragma unroll
    for (int i = 0; i < 4; i++) {
        #pragma unroll
        for (int j = 0; j < 4; j++) {
            int mrow = row0 + wm*64 + i*16 + g;
            int ncol = col0 + wn*32 + j*8 + 2*ql;
            float bx = bias[ncol], by = bias[ncol + 1];
            #pragma unroll
            for (int rr = 0; rr < 2; rr++) {
                int m = mrow + rr*8;
                float2 val = make_float2(acc[i][j][2*rr] + bx, acc[i][j][2*rr+1] + by);
                int b = m >> 10;
                int t = m & (T_ - 1);
                if (remap) {
                    val.x = tf32f(val.x); val.y = tf32f(val.y);
                    int h = ncol >> 6;
                    int d = ncol & 63;
                    *(float2*)&C[(((size_t)b*H_ + h)*T_ + t)*HD_ + d] = val;
                } else {
                    *(float2*)&C[(size_t)m * 768 + ncol] = val;
                }
            }
        }
    }
}

// ---------------- flash attention (tf32 mma + ldmatrix) -----------------------
// Bq=64, Bk=64, 4 warps; warp owns 16 q-rows. q/k/v pre-rounded tf32.
#define FQ 0
#define FK (64*68)
#define FV (2*64*68)
#define FP (3*64*68)
#define FM (4*64*68)
__global__ __launch_bounds__(128, 3)
void flash_kernel(const float* __restrict__ q,
                  const float* __restrict__ k,
                  const float* __restrict__ v,
                  const float* __restrict__ rel,
                  const float* __restrict__ mask,
                  const float* __restrict__ g1,
                  float* __restrict__ o)
{
    extern __shared__ float sm[];
    int bh = blockIdx.y;
    int b  = bh / H_;
    int h  = bh % H_;
    int q0 = blockIdx.x * 64;
    int tid  = threadIdx.x;
    int w    = tid >> 5;
    int lane = tid & 31;
    int g  = lane >> 2, ql = lane & 3;
    int r0 = w*16 + g;
    int r1 = r0 + 8;

    const float* qptr  = q + ((size_t)bh * T_ + q0) * HD_;
    const float* kbase = k + (size_t)bh * T_ * HD_;
    const float* vbase = v + (size_t)bh * T_ * HD_;
    const float* rbase = rel + (size_t)bh * T_ * T_;

    unsigned smb = sptr(sm);

    // ldmatrix lane addressing
    int rlA = ((lane >> 3) & 1)*8 + (lane & 7);
    int hA  = lane >> 4;
    int rlB = ((lane >> 4) & 1)*8 + (lane & 7);
    int hB  = (lane >> 3) & 1;
    unsigned qAoff = smb + (FQ + (w*16 + rlA)*68)*4;
    unsigned pAoff = smb + (FP + (w*16 + rlA)*68)*4;
    unsigned kBoff[4], vBoff[4];
    #pragma unroll
    for (int jj = 0; jj < 4; jj++) {
        kBoff[jj] = smb + (FK + (jj*16 + rlB)*68)*4;
        vBoff[jj] = smb + (FV + (jj*16 + rlB)*68)*4;
    }

    // stage Q via cp.async: 64 rows x 16 chunks = 1024 chunks, 8 per thread
    #pragma unroll
    for (int i = 0; i < 8; i++) {
        int j = tid + 128*i;
        int r = j >> 4, c = j & 15;
        cp16(smb + (FQ + r*68 + c*4)*4, qptr + (size_t)r*HD_ + c*4);
    }
    cp_commit();

    float ga0 = g1[(size_t)bh*T_ + q0 + r0];
    float ga1 = g1[(size_t)bh*T_ + q0 + r1];

    float m0 = -1e30f, m1 = -1e30f, l0 = 0.f, l1 = 0.f;
    float ov[8][4] = {};

    for (int kt = 0; kt < T_; kt += 64) {
        __syncthreads();
        // K tile via cp.async: full 64x64 tile
        #pragma unroll
        for (int i = 0; i < 8; i++) {
            int j = tid + 128*i;
            int r = j >> 4, c = j & 15;
            cp16(smb + (FK + r*68 + c*4)*4, kbase + (size_t)(kt + r)*HD_ + c*4);
        }
        cp_commit();
        // V tile transposed: Vt[d][kseq]
        #pragma unroll
        for (int it = 0; it < 8; it++) {
            int idx = tid + 128*it;
            int r = idx >> 4;            // kseq
            int c4 = (idx & 15) * 4;     // d
            float4 vv = *(const float4*)&vbase[(size_t)(kt + r)*HD_ + c4];
            sm[FV + (c4+0)*68 + r] = vv.x;
            sm[FV + (c4+1)*68 + r] = vv.y;
            sm[FV + (c4+2)*68 + r] = vv.z;
            sm[FV + (c4+3)*68 + r] = vv.w;
        }
        if (tid < 64) sm[FM + tid] = mask[(size_t)b*T_ + kt + tid];

        // rel bias fragments direct from global (overlaps cp.async)
        float rv[8][4];
        #pragma unroll
        for (int n = 0; n < 8; n++) {
            int c0 = kt + 8*n + 2*ql;
            rv[n][0] = rbase[(size_t)c0      * T_ + q0 + r0];
            rv[n][1] = rbase[(size_t)(c0+1)  * T_ + q0 + r0];
            rv[n][2] = rbase[(size_t)c0      * T_ + q0 + r1];
            rv[n][3] = rbase[(size_t)(c0+1)  * T_ + q0 + r1];
        }
        asm volatile("cp.async.wait_group 0;\n");
        __syncthreads();

        // ---- S = Q @ K^T ----
        float sc[8][4] = {};
        #pragma unroll
        for (int ks = 0; ks < 8; ks++) {
            unsigned ca  = (unsigned)((2*ks + hA)*16);
            unsigned cbk = (unsigned)((2*ks + hB)*16);
            unsigned qa0, qa1, qa2, qa3;
            ldsm4(qa0, qa1, qa2, qa3, qAoff + ca);
            #pragma unroll
            for (int jj = 0; jj < 4; jj++) {
                unsigned kb0, kb1, kb2, kb3;
                ldsm4(kb0, kb1, kb2, kb3, kBoff[jj] + cbk);
                mma8u(sc[2*jj],   qa0, qa1, qa2, qa3, kb0, kb1);
                mma8u(sc[2*jj+1], qa0, qa1, qa2, qa3, kb2, kb3);
            }
        }

        // ---- bias + mask + online softmax ----
        #pragma unroll
        for (int n = 0; n < 8; n++) {
            float mk0 = sm[FM + 8*n + 2*ql];
            float mk1 = sm[FM + 8*n + 2*ql + 1];
            sc[n][0] = sc[n][0]*0.125f + ga0*rv[n][0] + mk0;
            sc[n][1] = sc[n][1]*0.125f + ga0*rv[n][1] + mk1;
            sc[n][2] = sc[n][2]*0.125f + ga1*rv[n][2] + mk0;
            sc[n][3] = sc[n][3]*0.125f + ga1*rv[n][3] + mk1;
        }
        float mt0 = -1e30f, mt1 = -1e30f;
        #pragma unroll
        for (int n = 0; n < 8; n++) {
            mt0 = fmaxf(mt0, fmaxf(sc[n][0], sc[n][1]));
            mt1 = fmaxf(mt1, fmaxf(sc[n][2], sc[n][3]));
        }
        mt0 = fmaxf(mt0, __shfl_xor_sync(0xffffffffu, mt0, 1));
        mt0 = fmaxf(mt0, __shfl_xor_sync(0xffffffffu, mt0, 2));
        mt1 = fmaxf(mt1, __shfl_xor_sync(0xffffffffu, mt1, 1));
        mt1 = fmaxf(mt1, __shfl_xor_sync(0xffffffffu, mt1, 2));
        float mn0 = fmaxf(m0, mt0), mn1 = fmaxf(m1, mt1);
        float al0 = __expf(m0 - mn0), al1 = __expf(m1 - mn1);
        m0 = mn0; m1 = mn1;
        float s0 = 0.f, s1 = 0.f;
        #pragma unroll
        for (int n = 0; n < 8; n++) {
            sc[n][0] = __expf(sc[n][0] - mn0);
            sc[n][1] = __expf(sc[n][1] - mn0);
            sc[n][2] = __expf(sc[n][2] - mn1);
            sc[n][3] = __expf(sc[n][3] - mn1);
            s0 += sc[n][0] + sc[n][1];
            s1 += sc[n][2] + sc[n][3];
        }
        s0 += __shfl_xor_sync(0xffffffffu, s0, 1);
        s0 += __shfl_xor_sync(0xffffffffu, s0, 2);
        s1 += __shfl_xor_sync(0xffffffffu, s1, 1);
        s1 += __shfl_xor_sync(0xffffffffu, s1, 2);
        l0 = l0 * al0 + s0;
        l1 = l1 * al1 + s1;
        #pragma unroll
        for (int n = 0; n < 8; n++) {
            ov[n][0] *= al0; ov[n][1] *= al0;
            ov[n][2] *= al1; ov[n][3] *= al1;
        }

        // ---- store P (tf32-rounded) ----
        #pragma unroll
        for (int n = 0; n < 8; n++) {
            *(float2*)&sm[FP + r0*68 + 8*n + 2*ql] =
                make_float2(tf32f(sc[n][0]), tf32f(sc[n][1]));
            *(float2*)&sm[FP + r1*68 + 8*n + 2*ql] =
                make_float2(tf32f(sc[n][2]), tf32f(sc[n][3]));
        }
        __syncwarp();

        // ---- O += P @ V ----
        #pragma unroll
        for (int ks = 0; ks < 8; ks++) {
            unsigned ca  = (unsigned)((2*ks + hA)*16);
            unsigned cbv = (unsigned)((2*ks + hB)*16);
            unsigned pa0, pa1, pa2, pa3;
            ldsm4(pa0, pa1, pa2, pa3, pAoff + ca);
            #pragma unroll
            for (int jj = 0; jj < 4; jj++) {
                unsigned vb0, vb1, vb2, vb3;
                ldsm4(vb0, vb1, vb2, vb3, vBoff[jj] + cbv);
                mma8u(ov[2*jj],   pa0, pa1, pa2, pa3, vb0, vb1);
                mma8u(ov[2*jj+1], pa0, pa1, pa2, pa3, vb2, vb3);
            }
        }
    }

    // epilogue: normalize, tf32-round (feeds final GEMM), merge heads
    float inv0 = 1.f / l0, inv1 = 1.f / l1;
    #pragma unroll
    for (int n = 0; n < 8; n++) {
        int d = h*HD_ + 8*n + 2*ql;
        *(float2*)&o[((size_t)b*T_ + q0 + r0)*D_ + d] =
            make_float2(tf32f(ov[n][0]*inv0), tf32f(ov[n][1]*inv0));
        *(float2*)&o[((size_t)b*T_ + q0 + r1)*D_ + d] =
            make_float2(tf32f(ov[n][2]*inv1), tf32f(ov[n][3]*inv1));
    }
}

// ---------------- launch ------------------------------------------------------
extern "C" void kernel_launch(void* const* d_in, const int* in_sizes, int n_in,
                              void* d_out, int out_size)
{
    const float* x    = (const float*)d_in[0];
    const float* mask = (const float*)d_in[1];
    const float* rel  = (const float*)d_in[2];
    const float* Wq   = (const float*)d_in[3];
    const float* bq   = (const float*)d_in[4];
    const float* Wk   = (const float*)d_in[5];
    const float* bk   = (const float*)d_in[6];
    const float* Wv   = (const float*)d_in[7];
    const float* bv   = (const float*)d_in[8];
    const float* Wo   = (const float*)d_in[9];
    const float* bo   = (const float*)d_in[10];
    const float* Wg   = (const float*)d_in[11];
    const float* bg   = (const float*)d_in[12];
    const float* grep = (const float*)d_in[13];
    float* out = (float*)d_out;

    float *qb, *kb, *vb, *ob, *xr, *wr, *g1b;
    cudaGetSymbolAddress((void**)&qb,  g_q);
    cudaGetSymbolAddress((void**)&kb,  g_k);
    cudaGetSymbolAddress((void**)&vb,  g_v);
    cudaGetSymbolAddress((void**)&ob,  g_o);
    cudaGetSymbolAddress((void**)&xr,  g_xr);
    cudaGetSymbolAddress((void**)&wr,  g_w);
    cudaGetSymbolAddress((void**)&g1b, g_g1);

    // pre-round x and weights to tf32
    round_kernel<<<(BT_*D_/4 + 255)/256, 256>>>(x,  xr, BT_*D_/4);
    round_kernel<<<(D_*D_/4 + 255)/256, 256>>>(Wq, wr + 0*D_*D_, D_*D_/4);
    round_kernel<<<(D_*D_/4 + 255)/256, 256>>>(Wk, wr + 1*D_*D_, D_*D_/4);
    round_kernel<<<(D_*D_/4 + 255)/256, 256>>>(Wv, wr + 2*D_*D_, D_*D_/4);
    round_kernel<<<(D_*D_/4 + 255)/256, 256>>>(Wo, wr + 3*D_*D_, D_*D_/4);

    gate_kernel<<<(BT_*H_)/256, 256>>>(x, Wg, bg, grep, g1b);

    const int GSMEM = (2*AS_STAGE + 2*BS_STAGE) * 4;   // 66560 B
    cudaFuncSetAttribute(gemm_tf32, cudaFuncAttributeMaxDynamicSharedMemorySize, GSMEM);

    // fused QKV: grid.z = 3
    dim3 gqkv(D_/128, BT_/128, 3);   // (6, 64, 3)
    gemm_tf32<<<gqkv, 256, GSMEM>>>(xr, wr, bq, bk, bv, qb, kb, vb, 1);

    const int FSMEM = (4*64*68 + 64) * 4;    // 69888 B
    cudaFuncSetAttribute(flash_kernel, cudaFuncAttributeMaxDynamicSharedMemorySize, FSMEM);
    flash_kernel<<<dim3(T_/64, BH_), 128, FSMEM>>>(qb, kb, vb, rel, mask, g1b, ob);

    // output projection: grid.z = 1, W index 3
    dim3 go(D_/128, BT_/128, 1);
    gemm_tf32<<<go, 256, GSMEM>>>(ob, wr + 3*D_*D_, bo, bo, bo, out, out, out, 0);
}